// round 15
// baseline (speedup 1.0000x reference)
#include <cuda_runtime.h>
#include <cuda_bf16.h>

// TelephotoInterp R15: R14 (best 74.2us) with ONE change — lazy velocity loads.
// In the telephoto branch, rz and drift depend only on position; a particle can
// be provably rejected when rz is outside the slab widened by |drift|*VMAX
// (VMAX=64 >> any velocity component). Only band particles load velocities,
// cutting ~half the velocity stream (instructions and sectors).

__device__ __forceinline__ float fsqrt_ap(float x) {
    float r; asm("sqrt.approx.f32 %0, %1;" : "=f"(r) : "f"(x)); return r;
}
__device__ __forceinline__ float frcp_ap(float x) {
    float r; asm("rcp.approx.f32 %0, %1;" : "=f"(r) : "f"(x)); return r;
}
__device__ __forceinline__ float frsqrt_ap(float x) {
    float r; asm("rsqrt.approx.f32 %0, %1;" : "=f"(r) : "f"(x)); return r;
}
__device__ __forceinline__ void red_add_v4(float* addr, float a, float b, float c, float d) {
    asm volatile("red.global.add.v4.f32 [%0], {%1, %2, %3, %4};"
                 :: "l"(addr), "f"(a), "f"(b), "f"(c), "f"(d) : "memory");
}

__device__ __forceinline__ float wrapf(float g, float fres) {
    g = (g <  0.0f) ? g + fres : g;
    g = (g <  0.0f) ? g + fres : g;
    g = (g >= fres) ? g - fres : g;
    g = (g >= fres) ? g - fres : g;
    return g;
}

// CIC scatter of one particle (branch-free v4 path when res % 4 == 0).
__device__ __forceinline__ void scatter_cic(
    float* __restrict__ out, int res, float fres, bool v4ok,
    float X, float Y, float scale)
{
    const float xg = wrapf(X * scale, fres);
    const float yg = wrapf(Y * scale, fres);

    const int ix0 = (int)xg;
    const int iy0 = (int)yg;
    const float fx = xg - (float)ix0;
    const float fy = yg - (float)iy0;
    int ix1 = ix0 + 1; if (ix1 == res) ix1 = 0;

    const float w00 = (1.0f - fx) * (1.0f - fy);
    const float w10 = fx * (1.0f - fy);
    const float w01 = (1.0f - fx) * fy;
    const float w11 = fx * fy;

    if (v4ok) {
        const int o   = iy0 & 3;
        const int iyb = iy0 & ~3;
        const bool e0 = (o == 0), e1 = (o == 1), e2 = (o == 2), e3 = (o == 3);

        const float a0 = e0 ? w00 : 0.0f;
        const float a1 = e1 ? w00 : (e0 ? w01 : 0.0f);
        const float a2 = e2 ? w00 : (e1 ? w01 : 0.0f);
        const float a3 = e3 ? w00 : (e2 ? w01 : 0.0f);

        const float b0 = e0 ? w10 : 0.0f;
        const float b1 = e1 ? w10 : (e0 ? w11 : 0.0f);
        const float b2 = e2 ? w10 : (e1 ? w11 : 0.0f);
        const float b3 = e3 ? w10 : (e2 ? w11 : 0.0f);

        red_add_v4(&out[ix0 * res + iyb], a0, a1, a2, a3);
        red_add_v4(&out[ix1 * res + iyb], b0, b1, b2, b3);

        if (e3) {
            int iy1 = iy0 + 1; if (iy1 == res) iy1 = 0;   // iy1 % 4 == 0
            red_add_v4(&out[ix0 * res + iy1], w01, 0.0f, 0.0f, 0.0f);
            red_add_v4(&out[ix1 * res + iy1], w11, 0.0f, 0.0f, 0.0f);
        }
    } else {
        int iy1 = iy0 + 1; if (iy1 == res) iy1 = 0;
        atomicAdd(&out[ix0 * res + iy0], w00);
        atomicAdd(&out[ix1 * res + iy0], w10);
        atomicAdd(&out[ix0 * res + iy1], w01);
        atomicAdd(&out[ix1 * res + iy1], w11);
    }
}

__global__ void telephoto_paint_kernel(
    const float2* __restrict__ pos2,
    const float2* __restrict__ vel2,
    const float* __restrict__ rotations,
    const float* __restrict__ observer,
    const float* __restrict__ r_centers,
    const float* __restrict__ widths,
    const float* __restrict__ t_p,
    const float* __restrict__ maxd_p,
    const float* __restrict__ box_p,
    const int*   __restrict__ shell_p,
    const int*   __restrict__ rotidx_p,
    const int*   __restrict__ res_p,
    float* __restrict__ out,
    int n)   // n = number of particles
{
    const int t = blockIdx.x * blockDim.x + threadIdx.x;
    const int base = 2 * t;
    if (base >= n) return;

    // Scalar params (uniform broadcast loads)
    const int   shell = shell_p[0];
    const float rc    = r_centers[shell];
    const float w     = widths[shell];
    const float maxd  = maxd_p[0];
    const float box   = box_p[0];
    const int   res   = res_p[0];
    const float fres  = (float)res;
    const bool inside = (rc + 0.5f * w <= maxd);
    const bool v4ok   = ((res & 3) == 0);
    const float ox = observer[0], oy = observer[1], oz = observer[2];
    const float zlo = rc - 0.5f * w;
    const float zhi = rc + 0.5f * w;
    const float scale = (float)res / box;
    const float VMAX  = 64.0f;   // provable bound on |velocity component|

    const int cnt = (base + 1 < n) ? 2 : 1;

    if (inside) {
        // Pure passthrough paint — velocities never needed.
        float px[2], py[2], pz[2];
        if (cnt == 2) {
            const float2 pA = __ldcs(&pos2[3*t + 0]);
            const float2 pB = __ldcs(&pos2[3*t + 1]);
            const float2 pC = __ldcs(&pos2[3*t + 2]);
            px[0]=pA.x; py[0]=pA.y; pz[0]=pB.x;
            px[1]=pB.y; py[1]=pC.x; pz[1]=pC.y;
        } else {
            const float* pp = (const float*)pos2;
            px[0] = pp[3*base+0]; py[0] = pp[3*base+1]; pz[0] = pp[3*base+2];
        }
        #pragma unroll
        for (int k = 0; k < 2; k++) {
            if (k >= cnt) break;
            const float Z = pz[k];
            if (!(Z >= zlo && Z < zhi)) continue;
            scatter_cic(out, res, fres, v4ok, px[k], py[k], scale);
        }
        return;
    }

    // Telephoto branch
    const int ridx = rotidx_p[0] % 47;
    const float* __restrict__ M = rotations + 9 * ridx;
    const float m00=M[0], m01=M[1], m02=M[2];
    const float m10=M[3], m11=M[4], m12=M[5];
    const float m20=M[6], m21=M[7], m22=M[8];
    const float tt    = t_p[0];
    const float shift = floorf(rc / maxd) * maxd;
    const float gp_t  = tt * sqrtf(tt);

    float px[2], py[2], pz[2];
    if (cnt == 2) {
        const float2 pA = __ldcs(&pos2[3*t + 0]);
        const float2 pB = __ldcs(&pos2[3*t + 1]);
        const float2 pC = __ldcs(&pos2[3*t + 2]);
        px[0]=pA.x; py[0]=pA.y; pz[0]=pB.x;
        px[1]=pB.y; py[1]=pC.x; pz[1]=pC.y;
    } else {
        const float* pp = (const float*)pos2;
        px[0] = pp[3*base+0]; py[0] = pp[3*base+1]; pz[0] = pp[3*base+2];
    }

    // Phase 1: position-only geometry + provable band test (no velocity).
    float rxs[2], rys[2], rzs[2], drs[2];
    bool band[2] = {false, false};
    #pragma unroll
    for (int k = 0; k < 2; k++) {
        if (k >= cnt) break;
        const float qx = px[k] - ox, qy = py[k] - oy, qz = pz[k] - oz;
        const float rx = m00*qx + m01*qy + m02*qz;
        const float ry = m10*qx + m11*qy + m12*qz;
        const float rz = m20*qx + m21*qy + m22*qz + shift;

        const float dxd = rx - ox, dyd = ry - oy, dzd = rz - oz;
        const float d2   = fmaf(dxd, dxd, fmaf(dyd, dyd, dzd*dzd));
        const float dist = fsqrt_ap(d2);

        const float a_tgt = frcp_ap(fmaf(dist, (1.0f/3000.0f), 1.0f));
        const float gp_a  = a_tgt * fsqrt_ap(a_tgt);          // a^1.5
        const float inv_q = frsqrt_ap(fsqrt_ap(tt * a_tgt));  // (t*a)^-0.25
        const float drift = (gp_a - gp_t) * (2.0f/3.0f) * inv_q;

        rxs[k]=rx; rys[k]=ry; rzs[k]=rz; drs[k]=drift;
        const float mg = fabsf(drift) * VMAX;   // |drift * wz| <= mg
        const float Zc = rz + oz;
        band[k] = (Zc >= zlo - mg) && (Zc < zhi + mg);
    }

    if (!(band[0] || band[1])) return;   // provably no contribution

    // Phase 2: load velocities only for threads with band particles.
    float vx[2], vy[2], vz[2];
    if (cnt == 2) {
        const float2 vA = __ldcs(&vel2[3*t + 0]);
        const float2 vB = __ldcs(&vel2[3*t + 1]);
        const float2 vC = __ldcs(&vel2[3*t + 2]);
        vx[0]=vA.x; vy[0]=vA.y; vz[0]=vB.x;
        vx[1]=vB.y; vy[1]=vC.x; vz[1]=vC.y;
    } else {
        const float* vv = (const float*)vel2;
        vx[0] = vv[3*base+0]; vy[0] = vv[3*base+1]; vz[0] = vv[3*base+2];
    }

    #pragma unroll
    for (int k = 0; k < 2; k++) {
        if (k >= cnt) break;
        if (!band[k]) continue;

        const float drift = drs[k];
        const float wz = m20*vx[k] + m21*vy[k] + m22*vz[k];
        const float Z  = rzs[k] + drift * wz + oz;
        if (!(Z >= zlo && Z < zhi)) continue;   // exact test

        const float wx = m00*vx[k] + m01*vy[k] + m02*vz[k];
        const float wy = m10*vx[k] + m11*vy[k] + m12*vz[k];
        const float X = rxs[k] + drift * wx + ox;
        const float Y = rys[k] + drift * wy + oy;

        scatter_cic(out, res, fres, v4ok, X, Y, scale);
    }
}

extern "C" void kernel_launch(void* const* d_in, const int* in_sizes, int n_in,
                              void* d_out, int out_size) {
    const float* positions  = (const float*)d_in[0];
    const float* velocities = (const float*)d_in[1];
    const float* rotations  = (const float*)d_in[2];
    const float* observer   = (const float*)d_in[3];
    const float* r_centers  = (const float*)d_in[4];
    const float* widths     = (const float*)d_in[5];
    const float* t_p        = (const float*)d_in[6];
    const float* maxd_p     = (const float*)d_in[7];
    const float* box_p      = (const float*)d_in[8];
    const int*   shell_p    = (const int*)d_in[9];
    const int*   rotidx_p   = (const int*)d_in[10];
    const int*   res_p      = (const int*)d_in[11];
    float* out = (float*)d_out;

    const int n = in_sizes[0] / 3;

    cudaMemsetAsync(out, 0, (size_t)out_size * sizeof(float));

    const int threads = 256;
    const int nthreads_needed = (n + 1) / 2;
    const int blocks = (nthreads_needed + threads - 1) / threads;
    telephoto_paint_kernel<<<blocks, threads>>>(
        (const float2*)positions, (const float2*)velocities,
        rotations, observer, r_centers, widths,
        t_p, maxd_p, box_p, shell_p, rotidx_p, res_p, out, n);
}

// round 16
// speedup vs baseline: 1.1074x; 1.1074x over previous
#include <cuda_runtime.h>
#include <cuda_bf16.h>

// TelephotoInterp R16: R14 (best 74.2us) with ONE change — 512-thread blocks
// (same 1536 thr/SM at regs=40; amortizes the scalar-param preamble and halves
// block-scheduling events). Last untested launch parameter.

__device__ __forceinline__ float fsqrt_ap(float x) {
    float r; asm("sqrt.approx.f32 %0, %1;" : "=f"(r) : "f"(x)); return r;
}
__device__ __forceinline__ float frcp_ap(float x) {
    float r; asm("rcp.approx.f32 %0, %1;" : "=f"(r) : "f"(x)); return r;
}
__device__ __forceinline__ float frsqrt_ap(float x) {
    float r; asm("rsqrt.approx.f32 %0, %1;" : "=f"(r) : "f"(x)); return r;
}
__device__ __forceinline__ void red_add_v4(float* addr, float a, float b, float c, float d) {
    asm volatile("red.global.add.v4.f32 [%0], {%1, %2, %3, %4};"
                 :: "l"(addr), "f"(a), "f"(b), "f"(c), "f"(d) : "memory");
}

__device__ __forceinline__ float wrapf(float g, float fres) {
    g = (g <  0.0f) ? g + fres : g;
    g = (g <  0.0f) ? g + fres : g;
    g = (g >= fres) ? g - fres : g;
    g = (g >= fres) ? g - fres : g;
    return g;
}

__global__ void telephoto_paint_kernel(
    const float2* __restrict__ pos2,
    const float2* __restrict__ vel2,
    const float* __restrict__ rotations,
    const float* __restrict__ observer,
    const float* __restrict__ r_centers,
    const float* __restrict__ widths,
    const float* __restrict__ t_p,
    const float* __restrict__ maxd_p,
    const float* __restrict__ box_p,
    const int*   __restrict__ shell_p,
    const int*   __restrict__ rotidx_p,
    const int*   __restrict__ res_p,
    float* __restrict__ out,
    int n)   // n = number of particles
{
    const int t = blockIdx.x * blockDim.x + threadIdx.x;
    const int base = 2 * t;
    if (base >= n) return;

    // Scalar params (uniform broadcast loads)
    const int   shell = shell_p[0];
    const float rc    = r_centers[shell];
    const float w     = widths[shell];
    const float maxd  = maxd_p[0];
    const float box   = box_p[0];
    const int   res   = res_p[0];
    const float fres  = (float)res;
    const bool inside = (rc + 0.5f * w <= maxd);
    const bool v4ok   = ((res & 3) == 0);
    const float ox = observer[0], oy = observer[1], oz = observer[2];
    const float zlo = rc - 0.5f * w;
    const float zhi = rc + 0.5f * w;
    const float scale = (float)res / box;

    // Rotation / drift params (only meaningful for telephoto branch)
    float m00=1.f,m01=0.f,m02=0.f,m10=0.f,m11=1.f,m12=0.f,m20=0.f,m21=0.f,m22=1.f;
    float tt = 0.f, shift = 0.f, gp_t = 0.f;
    if (!inside) {
        const int ridx = rotidx_p[0] % 47;
        const float* __restrict__ M = rotations + 9 * ridx;
        m00=M[0]; m01=M[1]; m02=M[2];
        m10=M[3]; m11=M[4]; m12=M[5];
        m20=M[6]; m21=M[7]; m22=M[8];
        tt = t_p[0];
        shift = floorf(rc / maxd) * maxd;
        gp_t = tt * sqrtf(tt);   // uniform scalar, IEEE is fine
    }

    // 2 particles = 6 floats = 3 float2 per array (always 8B-aligned).
    // Front-batched streaming loads: max MLP, latency overlapped.
    float px[2], py[2], pz[2], vx[2], vy[2], vz[2];
    int cnt = 2;
    if (base + 1 < n) {
        const float2 pA = __ldcs(&pos2[3*t + 0]);   // x0 y0
        const float2 pB = __ldcs(&pos2[3*t + 1]);   // z0 x1
        const float2 pC = __ldcs(&pos2[3*t + 2]);   // y1 z1
        px[0]=pA.x; py[0]=pA.y; pz[0]=pB.x;
        px[1]=pB.y; py[1]=pC.x; pz[1]=pC.y;
        if (!inside) {
            const float2 vA = __ldcs(&vel2[3*t + 0]);
            const float2 vB = __ldcs(&vel2[3*t + 1]);
            const float2 vC = __ldcs(&vel2[3*t + 2]);
            vx[0]=vA.x; vy[0]=vA.y; vz[0]=vB.x;
            vx[1]=vB.y; vy[1]=vC.x; vz[1]=vC.y;
        }
    } else {
        cnt = 1;
        const float* pp = (const float*)pos2;
        const float* vv = (const float*)vel2;
        px[0] = pp[3*base+0]; py[0] = pp[3*base+1]; pz[0] = pp[3*base+2];
        if (!inside) {
            vx[0] = vv[3*base+0]; vy[0] = vv[3*base+1]; vz[0] = vv[3*base+2];
        }
    }

    #pragma unroll
    for (int k = 0; k < 2; k++) {
        if (k >= cnt) break;

        float X, Y;
        if (inside) {
            const float Z = pz[k];
            if (!(Z >= zlo && Z < zhi)) continue;   // sel==0 adds +0.0 -> skip
            X = px[k]; Y = py[k];
        } else {
            const float qx = px[k] - ox, qy = py[k] - oy, qz = pz[k] - oz;
            const float rx = m00*qx + m01*qy + m02*qz;
            const float ry = m10*qx + m11*qy + m12*qz;
            const float rz = m20*qx + m21*qy + m22*qz + shift;

            const float dxd = rx - ox, dyd = ry - oy, dzd = rz - oz;
            const float d2   = fmaf(dxd, dxd, fmaf(dyd, dyd, dzd*dzd));
            const float dist = fsqrt_ap(d2);

            const float a_tgt = frcp_ap(fmaf(dist, (1.0f/3000.0f), 1.0f));
            const float gp_a  = a_tgt * fsqrt_ap(a_tgt);          // a^1.5
            const float inv_q = frsqrt_ap(fsqrt_ap(tt * a_tgt));  // (t*a)^-0.25
            const float drift = (gp_a - gp_t) * (2.0f/3.0f) * inv_q;

            const float wz = m20*vx[k] + m21*vy[k] + m22*vz[k];
            const float Z  = rz + drift * wz + oz;
            if (!(Z >= zlo && Z < zhi)) continue;   // sel==0 adds +0.0 -> skip

            // Only accepted particles pay for X/Y
            const float wx = m00*vx[k] + m01*vy[k] + m02*vz[k];
            const float wy = m10*vx[k] + m11*vy[k] + m12*vz[k];
            X = rx + drift * wx + ox;
            Y = ry + drift * wy + oy;
        }

        // Float-domain periodic wrap, then floor (no integer modulo needed)
        const float xg = wrapf(X * scale, fres);
        const float yg = wrapf(Y * scale, fres);

        const int ix0 = (int)xg;        // xg in [0, fres) -> trunc == floor
        const int iy0 = (int)yg;
        const float fx = xg - (float)ix0;
        const float fy = yg - (float)iy0;
        int ix1 = ix0 + 1; if (ix1 == res) ix1 = 0;

        const float w00 = (1.0f - fx) * (1.0f - fy);
        const float w10 = fx * (1.0f - fy);
        const float w01 = (1.0f - fx) * fy;
        const float w11 = fx * fy;

        if (v4ok) {
            // Branch-free uniform scatter (see R11): one v4 per row at the 16B
            // window containing iy0, plus predicated spill v4 for o==3.
            const int o   = iy0 & 3;
            const int iyb = iy0 & ~3;

            const bool e0 = (o == 0), e1 = (o == 1), e2 = (o == 2), e3 = (o == 3);

            const float a0 = e0 ? w00 : 0.0f;
            const float a1 = e1 ? w00 : (e0 ? w01 : 0.0f);
            const float a2 = e2 ? w00 : (e1 ? w01 : 0.0f);
            const float a3 = e3 ? w00 : (e2 ? w01 : 0.0f);

            const float b0 = e0 ? w10 : 0.0f;
            const float b1 = e1 ? w10 : (e0 ? w11 : 0.0f);
            const float b2 = e2 ? w10 : (e1 ? w11 : 0.0f);
            const float b3 = e3 ? w10 : (e2 ? w11 : 0.0f);

            red_add_v4(&out[ix0 * res + iyb], a0, a1, a2, a3);
            red_add_v4(&out[ix1 * res + iyb], b0, b1, b2, b3);

            if (e3) {
                int iy1 = iy0 + 1; if (iy1 == res) iy1 = 0;   // iy1 % 4 == 0
                red_add_v4(&out[ix0 * res + iy1], w01, 0.0f, 0.0f, 0.0f);
                red_add_v4(&out[ix1 * res + iy1], w11, 0.0f, 0.0f, 0.0f);
            }
        } else {
            int iy1 = iy0 + 1; if (iy1 == res) iy1 = 0;
            atomicAdd(&out[ix0 * res + iy0], w00);
            atomicAdd(&out[ix1 * res + iy0], w10);
            atomicAdd(&out[ix0 * res + iy1], w01);
            atomicAdd(&out[ix1 * res + iy1], w11);
        }
    }
}

extern "C" void kernel_launch(void* const* d_in, const int* in_sizes, int n_in,
                              void* d_out, int out_size) {
    const float* positions  = (const float*)d_in[0];
    const float* velocities = (const float*)d_in[1];
    const float* rotations  = (const float*)d_in[2];
    const float* observer   = (const float*)d_in[3];
    const float* r_centers  = (const float*)d_in[4];
    const float* widths     = (const float*)d_in[5];
    const float* t_p        = (const float*)d_in[6];
    const float* maxd_p     = (const float*)d_in[7];
    const float* box_p      = (const float*)d_in[8];
    const int*   shell_p    = (const int*)d_in[9];
    const int*   rotidx_p   = (const int*)d_in[10];
    const int*   res_p      = (const int*)d_in[11];
    float* out = (float*)d_out;

    const int n = in_sizes[0] / 3;

    cudaMemsetAsync(out, 0, (size_t)out_size * sizeof(float));

    const int threads = 512;
    const int nthreads_needed = (n + 1) / 2;
    const int blocks = (nthreads_needed + threads - 1) / threads;
    telephoto_paint_kernel<<<blocks, threads>>>(
        (const float2*)positions, (const float2*)velocities,
        rotations, observer, r_centers, widths,
        t_p, maxd_p, box_p, shell_p, rotidx_p, res_p, out, n);
}

// round 17
// speedup vs baseline: 1.1341x; 1.0241x over previous
#include <cuda_runtime.h>
#include <cuda_bf16.h>

// TelephotoInterp FINAL (== R14, session best 74.2us bench / 71.4us kernel).
// 8.4M-particle telephoto transform + CIC paint onto 2048^2 grid.
//
// Established by 16 measured rounds:
//  - 2 particles/thread, front-batched float2 (LDG.64) streaming loads
//  - MUFU-approx drift chain (sqrt/rcp/rsqrt.approx), no Newton refinement
//  - float-domain periodic wrap (no integer %res division)
//  - branch-free scatter: per grid row one red.v4 at the 16B window holding
//    iy0 (weights placed by selects; padding zero-adds are free — LTS atomics
//    are op-limited, not word-limited) + predicated spill v4 for iy0%4==3
//  - floor: ~50us L2 atomic service (4.2M selected x 2.5 red ops) +
//    input-stream overlap; all other pipes have slack.

__device__ __forceinline__ float fsqrt_ap(float x) {
    float r; asm("sqrt.approx.f32 %0, %1;" : "=f"(r) : "f"(x)); return r;
}
__device__ __forceinline__ float frcp_ap(float x) {
    float r; asm("rcp.approx.f32 %0, %1;" : "=f"(r) : "f"(x)); return r;
}
__device__ __forceinline__ float frsqrt_ap(float x) {
    float r; asm("rsqrt.approx.f32 %0, %1;" : "=f"(r) : "f"(x)); return r;
}
__device__ __forceinline__ void red_add_v4(float* addr, float a, float b, float c, float d) {
    asm volatile("red.global.add.v4.f32 [%0], {%1, %2, %3, %4};"
                 :: "l"(addr), "f"(a), "f"(b), "f"(c), "f"(d) : "memory");
}

__device__ __forceinline__ float wrapf(float g, float fres) {
    g = (g <  0.0f) ? g + fres : g;
    g = (g <  0.0f) ? g + fres : g;
    g = (g >= fres) ? g - fres : g;
    g = (g >= fres) ? g - fres : g;
    return g;
}

__global__ void telephoto_paint_kernel(
    const float2* __restrict__ pos2,
    const float2* __restrict__ vel2,
    const float* __restrict__ rotations,
    const float* __restrict__ observer,
    const float* __restrict__ r_centers,
    const float* __restrict__ widths,
    const float* __restrict__ t_p,
    const float* __restrict__ maxd_p,
    const float* __restrict__ box_p,
    const int*   __restrict__ shell_p,
    const int*   __restrict__ rotidx_p,
    const int*   __restrict__ res_p,
    float* __restrict__ out,
    int n)   // n = number of particles
{
    const int t = blockIdx.x * blockDim.x + threadIdx.x;
    const int base = 2 * t;
    if (base >= n) return;

    // Scalar params (uniform broadcast loads)
    const int   shell = shell_p[0];
    const float rc    = r_centers[shell];
    const float w     = widths[shell];
    const float maxd  = maxd_p[0];
    const float box   = box_p[0];
    const int   res   = res_p[0];
    const float fres  = (float)res;
    const bool inside = (rc + 0.5f * w <= maxd);
    const bool v4ok   = ((res & 3) == 0);
    const float ox = observer[0], oy = observer[1], oz = observer[2];
    const float zlo = rc - 0.5f * w;
    const float zhi = rc + 0.5f * w;
    const float scale = (float)res / box;

    // Rotation / drift params (only meaningful for telephoto branch)
    float m00=1.f,m01=0.f,m02=0.f,m10=0.f,m11=1.f,m12=0.f,m20=0.f,m21=0.f,m22=1.f;
    float tt = 0.f, shift = 0.f, gp_t = 0.f;
    if (!inside) {
        const int ridx = rotidx_p[0] % 47;
        const float* __restrict__ M = rotations + 9 * ridx;
        m00=M[0]; m01=M[1]; m02=M[2];
        m10=M[3]; m11=M[4]; m12=M[5];
        m20=M[6]; m21=M[7]; m22=M[8];
        tt = t_p[0];
        shift = floorf(rc / maxd) * maxd;
        gp_t = tt * sqrtf(tt);   // uniform scalar, IEEE is fine
    }

    // 2 particles = 6 floats = 3 float2 per array (always 8B-aligned).
    // Front-batched streaming loads: max MLP, latency overlapped.
    float px[2], py[2], pz[2], vx[2], vy[2], vz[2];
    int cnt = 2;
    if (base + 1 < n) {
        const float2 pA = __ldcs(&pos2[3*t + 0]);   // x0 y0
        const float2 pB = __ldcs(&pos2[3*t + 1]);   // z0 x1
        const float2 pC = __ldcs(&pos2[3*t + 2]);   // y1 z1
        px[0]=pA.x; py[0]=pA.y; pz[0]=pB.x;
        px[1]=pB.y; py[1]=pC.x; pz[1]=pC.y;
        if (!inside) {
            const float2 vA = __ldcs(&vel2[3*t + 0]);
            const float2 vB = __ldcs(&vel2[3*t + 1]);
            const float2 vC = __ldcs(&vel2[3*t + 2]);
            vx[0]=vA.x; vy[0]=vA.y; vz[0]=vB.x;
            vx[1]=vB.y; vy[1]=vC.x; vz[1]=vC.y;
        }
    } else {
        cnt = 1;
        const float* pp = (const float*)pos2;
        const float* vv = (const float*)vel2;
        px[0] = pp[3*base+0]; py[0] = pp[3*base+1]; pz[0] = pp[3*base+2];
        if (!inside) {
            vx[0] = vv[3*base+0]; vy[0] = vv[3*base+1]; vz[0] = vv[3*base+2];
        }
    }

    #pragma unroll
    for (int k = 0; k < 2; k++) {
        if (k >= cnt) break;

        float X, Y;
        if (inside) {
            const float Z = pz[k];
            if (!(Z >= zlo && Z < zhi)) continue;   // sel==0 adds +0.0 -> skip
            X = px[k]; Y = py[k];
        } else {
            const float qx = px[k] - ox, qy = py[k] - oy, qz = pz[k] - oz;
            const float rx = m00*qx + m01*qy + m02*qz;
            const float ry = m10*qx + m11*qy + m12*qz;
            const float rz = m20*qx + m21*qy + m22*qz + shift;

            const float dxd = rx - ox, dyd = ry - oy, dzd = rz - oz;
            const float d2   = fmaf(dxd, dxd, fmaf(dyd, dyd, dzd*dzd));
            const float dist = fsqrt_ap(d2);

            const float a_tgt = frcp_ap(fmaf(dist, (1.0f/3000.0f), 1.0f));
            const float gp_a  = a_tgt * fsqrt_ap(a_tgt);          // a^1.5
            const float inv_q = frsqrt_ap(fsqrt_ap(tt * a_tgt));  // (t*a)^-0.25
            const float drift = (gp_a - gp_t) * (2.0f/3.0f) * inv_q;

            const float wz = m20*vx[k] + m21*vy[k] + m22*vz[k];
            const float Z  = rz + drift * wz + oz;
            if (!(Z >= zlo && Z < zhi)) continue;   // sel==0 adds +0.0 -> skip

            // Only accepted particles pay for X/Y
            const float wx = m00*vx[k] + m01*vy[k] + m02*vz[k];
            const float wy = m10*vx[k] + m11*vy[k] + m12*vz[k];
            X = rx + drift * wx + ox;
            Y = ry + drift * wy + oy;
        }

        // Float-domain periodic wrap, then floor (no integer modulo needed)
        const float xg = wrapf(X * scale, fres);
        const float yg = wrapf(Y * scale, fres);

        const int ix0 = (int)xg;        // xg in [0, fres) -> trunc == floor
        const int iy0 = (int)yg;
        const float fx = xg - (float)ix0;
        const float fy = yg - (float)iy0;
        int ix1 = ix0 + 1; if (ix1 == res) ix1 = 0;

        const float w00 = (1.0f - fx) * (1.0f - fy);
        const float w10 = fx * (1.0f - fy);
        const float w01 = (1.0f - fx) * fy;
        const float w11 = fx * fy;

        if (v4ok) {
            // Branch-free uniform scatter: one v4 per row at the 16B window
            // containing iy0, plus predicated spill v4 for o==3.
            const int o   = iy0 & 3;
            const int iyb = iy0 & ~3;

            const bool e0 = (o == 0), e1 = (o == 1), e2 = (o == 2), e3 = (o == 3);

            const float a0 = e0 ? w00 : 0.0f;
            const float a1 = e1 ? w00 : (e0 ? w01 : 0.0f);
            const float a2 = e2 ? w00 : (e1 ? w01 : 0.0f);
            const float a3 = e3 ? w00 : (e2 ? w01 : 0.0f);

            const float b0 = e0 ? w10 : 0.0f;
            const float b1 = e1 ? w10 : (e0 ? w11 : 0.0f);
            const float b2 = e2 ? w10 : (e1 ? w11 : 0.0f);
            const float b3 = e3 ? w10 : (e2 ? w11 : 0.0f);

            red_add_v4(&out[ix0 * res + iyb], a0, a1, a2, a3);
            red_add_v4(&out[ix1 * res + iyb], b0, b1, b2, b3);

            if (e3) {
                int iy1 = iy0 + 1; if (iy1 == res) iy1 = 0;   // iy1 % 4 == 0
                red_add_v4(&out[ix0 * res + iy1], w01, 0.0f, 0.0f, 0.0f);
                red_add_v4(&out[ix1 * res + iy1], w11, 0.0f, 0.0f, 0.0f);
            }
        } else {
            int iy1 = iy0 + 1; if (iy1 == res) iy1 = 0;
            atomicAdd(&out[ix0 * res + iy0], w00);
            atomicAdd(&out[ix1 * res + iy0], w10);
            atomicAdd(&out[ix0 * res + iy1], w01);
            atomicAdd(&out[ix1 * res + iy1], w11);
        }
    }
}

extern "C" void kernel_launch(void* const* d_in, const int* in_sizes, int n_in,
                              void* d_out, int out_size) {
    const float* positions  = (const float*)d_in[0];
    const float* velocities = (const float*)d_in[1];
    const float* rotations  = (const float*)d_in[2];
    const float* observer   = (const float*)d_in[3];
    const float* r_centers  = (const float*)d_in[4];
    const float* widths     = (const float*)d_in[5];
    const float* t_p        = (const float*)d_in[6];
    const float* maxd_p     = (const float*)d_in[7];
    const float* box_p      = (const float*)d_in[8];
    const int*   shell_p    = (const int*)d_in[9];
    const int*   rotidx_p   = (const int*)d_in[10];
    const int*   res_p      = (const int*)d_in[11];
    float* out = (float*)d_out;

    const int n = in_sizes[0] / 3;

    cudaMemsetAsync(out, 0, (size_t)out_size * sizeof(float));

    const int threads = 256;
    const int nthreads_needed = (n + 1) / 2;
    const int blocks = (nthreads_needed + threads - 1) / threads;
    telephoto_paint_kernel<<<blocks, threads>>>(
        (const float2*)positions, (const float2*)velocities,
        rotations, observer, r_centers, widths,
        t_p, maxd_p, box_p, shell_p, rotidx_p, res_p, out, n);
}